// round 2
// baseline (speedup 1.0000x reference)
#include <cuda_runtime.h>

#define KVOL 27
#define MAXN 131072

// Scratch (device globals — allocation rules forbid cudaMalloc)
__device__ __align__(16) static float g_pre[MAXN * 32];   // pre-BN conv output
__device__ static int   g_nbr[KVOL * MAXN];               // nbr[k][o] = input idx or -1
__device__ static float g_sum[32];
__device__ static float g_sumsq[32];

// packed fp32x2 FMA: d = a*b + d  (FFMA2, only reachable via PTX)
__device__ __forceinline__ void ffma2(unsigned long long& d,
                                      unsigned long long a,
                                      unsigned long long b) {
    asm("fma.rn.f32x2 %0, %1, %2, %3;" : "=l"(d) : "l"(a), "l"(b), "l"(d));
}
__device__ __forceinline__ float2 unpack2(unsigned long long v) {
    float2 r;
    asm("mov.b64 {%0, %1}, %2;" : "=f"(r.x), "=f"(r.y) : "l"(v));
    return r;
}

// ---------------------------------------------------------------------------
// K1: init nbr table to -1, zero channel sums
// ---------------------------------------------------------------------------
__global__ void k_init(int total) {
    int idx = blockIdx.x * blockDim.x + threadIdx.x;
    int stride = gridDim.x * blockDim.x;
    for (int j = idx; j < total; j += stride) g_nbr[j] = -1;
    if (idx < 32) { g_sum[idx] = 0.f; g_sumsq[idx] = 0.f; }
}

// ---------------------------------------------------------------------------
// K2: scatter kernel maps -> dense nbr table.
// Validity inferred from out_idx monotonicity (valid entries form a strictly
// increasing prefix per k; padding is zeros, so the local test is exact).
// ---------------------------------------------------------------------------
__global__ void k_scatter(const int* __restrict__ out_idx,
                          const int* __restrict__ in_idx, int N) {
    int p = blockIdx.x * blockDim.x + threadIdx.x;
    int k = blockIdx.y;
    if (p >= N) return;
    long long base = (long long)k * N;
    int o = out_idx[base + p];
    bool valid = (p == 0) || (o > out_idx[base + p - 1]);
    if (valid) g_nbr[base + o] = in_idx[base + p];
}

// ---------------------------------------------------------------------------
// K3: output-stationary conv. 64 voxels / block, 256 threads.
// Thread (cg = tid&7, vg = tid>>3) computes 2 voxels x 4 channels using
// packed fp32x2 FMAs. Gathered feats are stored DUPLICATED (x,x) in smem so
// FFMA2 operands need no pack ops; W[k] is staged through smem (no inner-loop
// LDG). Row stride 34 ull (272B) => conflict-free broadcast LDS.64.
// ---------------------------------------------------------------------------
__global__ __launch_bounds__(256) void k_conv(const float* __restrict__ feats,
                                              const float* __restrict__ W,
                                              int N) {
    __shared__ __align__(16) unsigned long long f_s2[64 * 34];  // 17408 B
    __shared__ __align__(16) float w_s[1024];                   //  4096 B
    __shared__ float s_red[2 * 8 * 32];                         //  2048 B
    const int tid = threadIdx.x;
    const int cg  = tid & 7;      // channel group: channels [cg*4, cg*4+4)
    const int vg  = tid >> 3;     // voxel group: voxels vg*2, vg*2+1
    const int v0  = vg * 2;
    const int obase = blockIdx.x * 64;

    unsigned long long acc00 = 0ull, acc01 = 0ull;  // voxel v0:   ch pairs
    unsigned long long acc10 = 0ull, acc11 = 0ull;  // voxel v0+1: ch pairs

    for (int k = 0; k < KVOL; ++k) {
        __syncthreads();  // previous-iteration readers done before overwrite

        // stage W[k] (1024 floats): one float4 per thread
        {
            float4 wv = *(const float4*)(W + k * 1024 + tid * 4);
            *(float4*)(w_s + tid * 4) = wv;
        }
        // gather 64 rows x 32 floats, duplicated (x,x) into smem
        const int* nbr_k = g_nbr + (long long)k * N + obase;
        #pragma unroll
        for (int t = 0; t < 2; ++t) {
            int j = tid + t * 256;
            int v = j >> 3, q = j & 7;
            int src = nbr_k[v];
            float4 val = make_float4(0.f, 0.f, 0.f, 0.f);
            if (src >= 0)
                val = *(const float4*)(feats + src * 32 + q * 4);
            float4* dst = (float4*)f_s2 + (v * 17 + 2 * q);  // 34 ull = 17 float4
            dst[0] = make_float4(val.x, val.x, val.y, val.y);
            dst[1] = make_float4(val.z, val.z, val.w, val.w);
        }
        __syncthreads();

        const unsigned long long* f0 = f_s2 + v0 * 34;
        const float* wp = w_s + cg * 4;
        #pragma unroll
        for (int i = 0; i < 32; ++i) {
            unsigned long long x0 = f0[i];
            unsigned long long x1 = f0[34 + i];
            unsigned long long w01 = *(const unsigned long long*)(wp + i * 32);
            unsigned long long w23 = *(const unsigned long long*)(wp + i * 32 + 2);
            ffma2(acc00, x0, w01);
            ffma2(acc01, x0, w23);
            ffma2(acc10, x1, w01);
            ffma2(acc11, x1, w23);
        }
    }

    float2 p00 = unpack2(acc00), p01 = unpack2(acc01);
    float2 p10 = unpack2(acc10), p11 = unpack2(acc11);
    float a00 = p00.x, a01 = p00.y, a02 = p01.x, a03 = p01.y;
    float a10 = p10.x, a11 = p10.y, a12 = p11.x, a13 = p11.y;

    // write pre-BN rows
    {
        int row0 = (obase + v0) * 32 + cg * 4;
        *(float4*)(g_pre + row0)      = make_float4(a00, a01, a02, a03);
        *(float4*)(g_pre + row0 + 32) = make_float4(a10, a11, a12, a13);
    }

    // per-channel sum / sumsq reduction
    float s0 = a00 + a10, s1 = a01 + a11, s2 = a02 + a12, s3 = a03 + a13;
    float q0 = a00 * a00 + a10 * a10, q1 = a01 * a01 + a11 * a11;
    float q2 = a02 * a02 + a12 * a12, q3 = a03 * a03 + a13 * a13;
    #pragma unroll
    for (int off = 16; off >= 8; off >>= 1) {
        s0 += __shfl_xor_sync(0xffffffffu, s0, off);
        s1 += __shfl_xor_sync(0xffffffffu, s1, off);
        s2 += __shfl_xor_sync(0xffffffffu, s2, off);
        s3 += __shfl_xor_sync(0xffffffffu, s3, off);
        q0 += __shfl_xor_sync(0xffffffffu, q0, off);
        q1 += __shfl_xor_sync(0xffffffffu, q1, off);
        q2 += __shfl_xor_sync(0xffffffffu, q2, off);
        q3 += __shfl_xor_sync(0xffffffffu, q3, off);
    }
    int lane = tid & 31, warp = tid >> 5;
    if (lane < 8) {
        float* sr = s_red + warp * 32 + lane * 4;
        sr[0] = s0; sr[1] = s1; sr[2] = s2; sr[3] = s3;
        float* qr = s_red + 256 + warp * 32 + lane * 4;
        qr[0] = q0; qr[1] = q1; qr[2] = q2; qr[3] = q3;
    }
    __syncthreads();
    if (tid < 32) {
        float ts = 0.f, tq = 0.f;
        #pragma unroll
        for (int w = 0; w < 8; ++w) {
            ts += s_red[w * 32 + tid];
            tq += s_red[256 + w * 32 + tid];
        }
        atomicAdd(&g_sum[tid], ts);
        atomicAdd(&g_sumsq[tid], tq);
    }
}

// ---------------------------------------------------------------------------
// K4: BN (batch stats, biased var) + ReLU
// ---------------------------------------------------------------------------
__global__ void k_bnrelu(const float* __restrict__ gamma,
                         const float* __restrict__ beta,
                         float* __restrict__ out, int N) {
    __shared__ float s_scale[32], s_shift[32];
    int tid = threadIdx.x;
    if (tid < 32) {
        float invN = 1.0f / (float)N;
        float mean = g_sum[tid] * invN;
        float var  = g_sumsq[tid] * invN - mean * mean;
        float sc   = gamma[tid] * rsqrtf(var + 1e-5f);
        s_scale[tid] = sc;
        s_shift[tid] = fmaf(-mean, sc, beta[tid]);
    }
    __syncthreads();
    long long total = (long long)N * 8;  // float4s
    for (long long j = blockIdx.x * (long long)blockDim.x + tid; j < total;
         j += (long long)gridDim.x * blockDim.x) {
        int c = ((int)(j & 7)) * 4;
        float4 v = *(const float4*)(g_pre + j * 4);
        float4 r;
        r.x = fmaxf(fmaf(v.x, s_scale[c + 0], s_shift[c + 0]), 0.f);
        r.y = fmaxf(fmaf(v.y, s_scale[c + 1], s_shift[c + 1]), 0.f);
        r.z = fmaxf(fmaf(v.z, s_scale[c + 2], s_shift[c + 2]), 0.f);
        r.w = fmaxf(fmaf(v.w, s_scale[c + 3], s_shift[c + 3]), 0.f);
        *(float4*)(out + j * 4) = r;
    }
}

// ---------------------------------------------------------------------------
// Launch. Inputs (metadata order): feats, W, gamma, beta, in_idx, out_idx, mask
// (mask deliberately unused — validity comes from out_idx monotonicity).
// ---------------------------------------------------------------------------
extern "C" void kernel_launch(void* const* d_in, const int* in_sizes, int n_in,
                              void* d_out, int out_size) {
    const float* feats   = (const float*)d_in[0];
    const float* W       = (const float*)d_in[1];
    const float* gamma   = (const float*)d_in[2];
    const float* beta    = (const float*)d_in[3];
    const int*   in_idx  = (const int*)d_in[4];
    const int*   out_idx = (const int*)d_in[5];
    const int N = in_sizes[0] / 32;

    k_init<<<1024, 256>>>(KVOL * N);

    dim3 sg((N + 255) / 256, KVOL);
    k_scatter<<<sg, 256>>>(out_idx, in_idx, N);

    k_conv<<<(N + 63) / 64, 256>>>(feats, W, N);

    k_bnrelu<<<1024, 256>>>(gamma, beta, (float*)d_out, N);
}

// round 5
// speedup vs baseline: 1.5368x; 1.5368x over previous
#include <cuda_runtime.h>
#include <cstdint>

#define KVOL 27
#define MAXN 131072
#define TILE_M 128

// ---------------------------------------------------------------------------
// Scratch (device globals — allocation rules forbid cudaMalloc)
// ---------------------------------------------------------------------------
__device__ static int   g_nbr[KVOL * MAXN];               // nbr[k][o] = in idx or -1
__device__ __align__(16) static float g_wt[KVOL * 1024];  // Wt[k][o][i], tf32-rounded
__device__ static float g_sum[32];
__device__ static float g_sumsq[32];

// ---------------------------------------------------------------------------
// K1: init nbr table to -1, zero channel sums
// ---------------------------------------------------------------------------
__global__ void k_init(int total) {
    int idx = blockIdx.x * blockDim.x + threadIdx.x;
    int stride = gridDim.x * blockDim.x;
    for (int j = idx; j < total; j += stride) g_nbr[j] = -1;
    if (idx < 32) { g_sum[idx] = 0.f; g_sumsq[idx] = 0.f; }
}

// ---------------------------------------------------------------------------
// K2: scatter kernel maps -> dense nbr table (validity from out_idx
// monotonicity: valid entries form a strictly increasing prefix per k).
// ---------------------------------------------------------------------------
__global__ void k_scatter(const int* __restrict__ out_idx,
                          const int* __restrict__ in_idx, int N) {
    int p = blockIdx.x * blockDim.x + threadIdx.x;
    int k = blockIdx.y;
    if (p >= N) return;
    long long base = (long long)k * N;
    int o = out_idx[base + p];
    bool valid = (p == 0) || (o > out_idx[base + p - 1]);
    if (valid) g_nbr[base + o] = in_idx[base + p];
}

// ---------------------------------------------------------------------------
// K2b: W[k][i][o] -> Wt[k][o][i], rounded to tf32 (rna) once, up front.
// ---------------------------------------------------------------------------
__global__ void k_wt(const float* __restrict__ W) {
    int k = blockIdx.x;
    for (int j = threadIdx.x; j < 1024; j += blockDim.x) {
        int o = j >> 5, i = j & 31;
        float v = W[k * 1024 + i * 32 + o];
        uint32_t t;
        asm("cvt.rna.tf32.f32 %0, %1;" : "=r"(t) : "f"(v));
        g_wt[k * 1024 + o * 32 + i] = __uint_as_float(t);
    }
}

// ---------------------------------------------------------------------------
// Fragment loads from XOR-swizzled smem tiles (32-float rows, 128B).
// Swizzle: 4-float group gq of row r lives at group gq ^ (r & 7).
// This makes all mma fragment LDS patterns bank-conflict-free.
// ---------------------------------------------------------------------------
__device__ __forceinline__ uint32_t ld_a(const float* a_s, int row, int col) {
    int phys = ((((col >> 2) ^ row) & 7) << 2) | (col & 3);
    float v = a_s[(row << 5) + phys];
    uint32_t t;
    asm("cvt.rna.tf32.f32 %0, %1;" : "=r"(t) : "f"(v));
    return t;
}
__device__ __forceinline__ uint32_t ld_b(const float* w_s, int o, int i) {
    int phys = ((((i >> 2) ^ o) & 7) << 2) | (i & 3);
    return __float_as_uint(w_s[(o << 5) + phys]);  // pre-rounded tf32
}

// ---------------------------------------------------------------------------
// K3: mma.sync tf32 gather-GEMM. One CTA / 128-voxel tile, 256 thr = 8 warps.
// Warp w computes rows [w*16, w*16+16) x 32 channels, accumulating in regs
// across all 27 offsets. Writes PRE-BN rows to out + folds BN sums.
// ---------------------------------------------------------------------------
__global__ __launch_bounds__(256) void k_conv_mma(const float* __restrict__ feats,
                                                  float* __restrict__ out, int N) {
    __shared__ __align__(16) float a_s[TILE_M * 32];  // 16384 B
    __shared__ __align__(16) float w_s[32 * 32];      //  4096 B
    __shared__ float s_red[2 * 8 * 32];               //  2048 B
    const int tid  = threadIdx.x;
    const int w    = tid >> 5;
    const int lane = tid & 31;
    const int g    = lane >> 2;   // group id (row within fragment)
    const int q    = lane & 3;    // thread-in-group (col within fragment)
    const int v0   = w * 16;      // warp's row base in tile
    const int obase = blockIdx.x * TILE_M;

    float c_[4][4];               // [ntile][{r0c0, r0c1, r1c0, r1c1}]
    #pragma unroll
    for (int nt = 0; nt < 4; ++nt)
        c_[nt][0] = c_[nt][1] = c_[nt][2] = c_[nt][3] = 0.f;

    for (int k = 0; k < KVOL; ++k) {
        __syncthreads();  // previous-iteration readers done before overwrite
        // stage Wt[k]: 1024 floats, one float4/thread, swizzled rows
        {
            int o = tid >> 3, i4 = tid & 7;
            float4 wv = *(const float4*)(g_wt + k * 1024 + o * 32 + i4 * 4);
            *(float4*)(w_s + o * 32 + ((i4 ^ (o & 7)) << 2)) = wv;
        }
        // gather A: 128 rows x 32 floats (4 float4/thread), zero-fill missing
        const int* nbr_k = g_nbr + (long long)k * N + obase;
        #pragma unroll
        for (int t = 0; t < 4; ++t) {
            int j = tid + t * 256;
            int v = j >> 3, qq = j & 7;
            int src = (obase + v < N) ? nbr_k[v] : -1;
            float4 val = make_float4(0.f, 0.f, 0.f, 0.f);
            if (src >= 0) val = *(const float4*)(feats + src * 32 + qq * 4);
            *(float4*)(a_s + v * 32 + ((qq ^ (v & 7)) << 2)) = val;
        }
        __syncthreads();

        #pragma unroll
        for (int ks = 0; ks < 4; ++ks) {
            int col0 = ks * 8 + q, col1 = col0 + 4;
            int r0 = v0 + g, r1 = r0 + 8;
            uint32_t a0 = ld_a(a_s, r0, col0);
            uint32_t a1 = ld_a(a_s, r1, col0);
            uint32_t a2 = ld_a(a_s, r0, col1);
            uint32_t a3 = ld_a(a_s, r1, col1);
            #pragma unroll
            for (int nt = 0; nt < 4; ++nt) {
                int o = nt * 8 + g;
                uint32_t b0 = ld_b(w_s, o, col0);
                uint32_t b1 = ld_b(w_s, o, col1);
                asm volatile(
                    "mma.sync.aligned.m16n8k8.row.col.f32.tf32.tf32.f32 "
                    "{%0,%1,%2,%3}, {%4,%5,%6,%7}, {%8,%9}, {%0,%1,%2,%3};"
                    : "+f"(c_[nt][0]), "+f"(c_[nt][1]),
                      "+f"(c_[nt][2]), "+f"(c_[nt][3])
                    : "r"(a0), "r"(a1), "r"(a2), "r"(a3), "r"(b0), "r"(b1));
            }
        }
    }

    // ---- epilogue: store pre-BN rows -------------------------------------
    int r0g = obase + v0 + g;
    int r1g = r0g + 8;
    #pragma unroll
    for (int nt = 0; nt < 4; ++nt) {
        if (r0g < N)
            *(float2*)(out + (long long)r0g * 32 + nt * 8 + 2 * q) =
                make_float2(c_[nt][0], c_[nt][1]);
        if (r1g < N)
            *(float2*)(out + (long long)r1g * 32 + nt * 8 + 2 * q) =
                make_float2(c_[nt][2], c_[nt][3]);
    }

    // ---- BN sums: padding rows are exactly zero, safe to include ----------
    float s[8], sq[8];
    #pragma unroll
    for (int nt = 0; nt < 4; ++nt) {
        s[nt * 2 + 0] = c_[nt][0] + c_[nt][2];
        s[nt * 2 + 1] = c_[nt][1] + c_[nt][3];
        sq[nt * 2 + 0] = c_[nt][0] * c_[nt][0] + c_[nt][2] * c_[nt][2];
        sq[nt * 2 + 1] = c_[nt][1] * c_[nt][1] + c_[nt][3] * c_[nt][3];
    }
    #pragma unroll
    for (int off = 16; off >= 4; off >>= 1) {  // reduce over g, keep q
        #pragma unroll
        for (int e = 0; e < 8; ++e) {
            s[e]  += __shfl_xor_sync(~0u, s[e], off);
            sq[e] += __shfl_xor_sync(~0u, sq[e], off);
        }
    }
    if (lane < 4) {
        #pragma unroll
        for (int nt = 0; nt < 4; ++nt) {
            int ch = nt * 8 + 2 * lane;
            s_red[w * 32 + ch]           = s[nt * 2 + 0];
            s_red[w * 32 + ch + 1]       = s[nt * 2 + 1];
            s_red[256 + w * 32 + ch]     = sq[nt * 2 + 0];
            s_red[256 + w * 32 + ch + 1] = sq[nt * 2 + 1];
        }
    }
    __syncthreads();
    if (tid < 32) {
        float ts = 0.f, tq = 0.f;
        #pragma unroll
        for (int ww = 0; ww < 8; ++ww) {
            ts += s_red[ww * 32 + tid];
            tq += s_red[256 + ww * 32 + tid];
        }
        atomicAdd(&g_sum[tid], ts);
        atomicAdd(&g_sumsq[tid], tq);
    }
}

// ---------------------------------------------------------------------------
// K4: BN (batch stats, biased var) + ReLU, in place on out
// ---------------------------------------------------------------------------
__global__ void k_bnrelu(const float* __restrict__ gamma,
                         const float* __restrict__ beta,
                         float* __restrict__ out, int N) {
    __shared__ float s_scale[32], s_shift[32];
    int tid = threadIdx.x;
    if (tid < 32) {
        float invN = 1.0f / (float)N;
        float mean = g_sum[tid] * invN;
        float var  = g_sumsq[tid] * invN - mean * mean;
        float sc   = gamma[tid] * rsqrtf(var + 1e-5f);
        s_scale[tid] = sc;
        s_shift[tid] = fmaf(-mean, sc, beta[tid]);
    }
    __syncthreads();
    long long total = (long long)N * 8;
    for (long long j = blockIdx.x * (long long)blockDim.x + tid; j < total;
         j += (long long)gridDim.x * blockDim.x) {
        int c = ((int)(j & 7)) * 4;
        float4 v = *(const float4*)(out + j * 4);
        float4 r;
        r.x = fmaxf(fmaf(v.x, s_scale[c + 0], s_shift[c + 0]), 0.f);
        r.y = fmaxf(fmaf(v.y, s_scale[c + 1], s_shift[c + 1]), 0.f);
        r.z = fmaxf(fmaf(v.z, s_scale[c + 2], s_shift[c + 2]), 0.f);
        r.w = fmaxf(fmaf(v.w, s_scale[c + 3], s_shift[c + 3]), 0.f);
        *(float4*)(out + j * 4) = r;
    }
}

// ---------------------------------------------------------------------------
// Launch. Inputs: feats, W, gamma, beta, in_idx, out_idx, mask (mask unused)
// ---------------------------------------------------------------------------
extern "C" void kernel_launch(void* const* d_in, const int* in_sizes, int n_in,
                              void* d_out, int out_size) {
    const float* feats   = (const float*)d_in[0];
    const float* W       = (const float*)d_in[1];
    const float* gamma   = (const float*)d_in[2];
    const float* beta    = (const float*)d_in[3];
    const int*   in_idx  = (const int*)d_in[4];
    const int*   out_idx = (const int*)d_in[5];
    const int N = in_sizes[0] / 32;
    float* out = (float*)d_out;

    k_init<<<1024, 256>>>(KVOL * N);
    dim3 sg((N + 255) / 256, KVOL);
    k_scatter<<<sg, 256>>>(out_idx, in_idx, N);
    k_wt<<<KVOL, 256>>>(W);
    k_conv_mma<<<(N + TILE_M - 1) / TILE_M, 256>>>(feats, out, N);
    k_bnrelu<<<1024, 256>>>(gamma, beta, out, N);
}

// round 6
// speedup vs baseline: 1.7312x; 1.1264x over previous
#include <cuda_runtime.h>
#include <cstdint>

#define KVOL 27
#define MAXN 131072
#define TILE_M 128

// ---------------------------------------------------------------------------
// Scratch (device globals — allocation rules forbid cudaMalloc)
// ---------------------------------------------------------------------------
__device__ static int   g_nbr[KVOL * MAXN];               // nbr[k][o] = in idx or -1
__device__ __align__(16) static float g_wt[KVOL * 1024];  // Wt[k][o][i], tf32-rounded
__device__ static float g_sum[32];
__device__ static float g_sumsq[32];

// ---------------------------------------------------------------------------
// cp.async helpers (Ampere+; legal under compute_100)
// ---------------------------------------------------------------------------
__device__ __forceinline__ uint32_t smem_u32(const void* p) {
    uint32_t a;
    asm("{ .reg .u64 t; cvta.to.shared.u64 t, %1; cvt.u32.u64 %0, t; }"
        : "=r"(a) : "l"(p));
    return a;
}
// 16B async copy; src_sz = 16 copies, src_sz = 0 writes zeros (no read)
__device__ __forceinline__ void cp_async16(uint32_t dst, const void* src, int src_sz) {
    asm volatile("cp.async.ca.shared.global [%0], [%1], 16, %2;"
                 :: "r"(dst), "l"(src), "r"(src_sz));
}
#define CP_COMMIT() asm volatile("cp.async.commit_group;" ::: "memory")
#define CP_WAIT0()  asm volatile("cp.async.wait_group 0;" ::: "memory")

// ---------------------------------------------------------------------------
// K1: init nbr table to -1, zero channel sums
// ---------------------------------------------------------------------------
__global__ void k_init(int total) {
    int idx = blockIdx.x * blockDim.x + threadIdx.x;
    int stride = gridDim.x * blockDim.x;
    for (int j = idx; j < total; j += stride) g_nbr[j] = -1;
    if (idx < 32) { g_sum[idx] = 0.f; g_sumsq[idx] = 0.f; }
}

// ---------------------------------------------------------------------------
// K2: scatter kernel maps -> dense nbr table (validity from out_idx
// monotonicity: valid entries form a strictly increasing prefix per k).
// ---------------------------------------------------------------------------
__global__ void k_scatter(const int* __restrict__ out_idx,
                          const int* __restrict__ in_idx, int N) {
    int p = blockIdx.x * blockDim.x + threadIdx.x;
    int k = blockIdx.y;
    if (p >= N) return;
    long long base = (long long)k * N;
    int o = out_idx[base + p];
    bool valid = (p == 0) || (o > out_idx[base + p - 1]);
    if (valid) g_nbr[base + o] = in_idx[base + p];
}

// ---------------------------------------------------------------------------
// K2b: W[k][i][o] -> Wt[k][o][i], rounded to tf32 (rna) once, up front.
// Rows are stored PRE-SWIZZLED so the conv kernel can cp.async them directly.
// ---------------------------------------------------------------------------
__global__ void k_wt(const float* __restrict__ W) {
    int k = blockIdx.x;
    for (int j = threadIdx.x; j < 1024; j += blockDim.x) {
        int o = j >> 5, i = j & 31;
        float v = W[k * 1024 + i * 32 + o];
        uint32_t t;
        asm("cvt.rna.tf32.f32 %0, %1;" : "=r"(t) : "f"(v));
        // swizzled column position within row o: group (i>>2) ^ (o&7)
        int phys = ((((i >> 2) ^ o) & 7) << 2) | (i & 3);
        g_wt[k * 1024 + o * 32 + phys] = __uint_as_float(t);
    }
}

// ---------------------------------------------------------------------------
// Fragment loads from XOR-swizzled smem tiles (32-float rows, 128B).
// Swizzle: 4-float group gq of row r lives at group gq ^ (r & 7).
// ---------------------------------------------------------------------------
__device__ __forceinline__ uint32_t ld_a(const float* a_s, int row, int col) {
    int phys = ((((col >> 2) ^ row) & 7) << 2) | (col & 3);
    float v = a_s[(row << 5) + phys];
    uint32_t t;
    asm("cvt.rna.tf32.f32 %0, %1;" : "=r"(t) : "f"(v));
    return t;
}
__device__ __forceinline__ uint32_t ld_b(const float* w_s, int o, int i) {
    int phys = ((((i >> 2) ^ o) & 7) << 2) | (i & 3);
    return __float_as_uint(w_s[(o << 5) + phys]);  // pre-rounded tf32
}

// ---------------------------------------------------------------------------
// K3: cp.async double-buffered mma.sync tf32 gather-GEMM.
// One CTA / 128-voxel tile, 256 thr = 8 warps; warp w owns rows [w*16,w*16+16).
// While stage k is consumed by MMAs, stage k+1 is gathered via cp.async.
// ---------------------------------------------------------------------------
__global__ __launch_bounds__(256) void k_conv_mma(const float* __restrict__ feats,
                                                  float* __restrict__ out, int N) {
    __shared__ __align__(16) float a_s[2][TILE_M * 32];  // 2 x 16384 B
    __shared__ __align__(16) float w_s[2][32 * 32];      // 2 x  4096 B
    __shared__ float s_red[2 * 8 * 32];                  //      2048 B
    const int tid  = threadIdx.x;
    const int w    = tid >> 5;
    const int lane = tid & 31;
    const int g    = lane >> 2;
    const int q    = lane & 3;
    const int v0   = w * 16;
    const int obase = blockIdx.x * TILE_M;

    // this thread's fixed gather slots: 4 x (row v, group qq), swizzled dst
    const int v_[4]  = { (tid + 0) >> 3, (tid + 256) >> 3,
                         (tid + 512) >> 3, (tid + 768) >> 3 };
    const int qq_ = tid & 7;  // same for all 4 since stride 256 ≡ 0 (mod 8)... 
    // NOTE: (tid + t*256) & 7 == tid & 7, and rows differ by 32.

    uint32_t a_dst[2][4], w_dst[2];
    #pragma unroll
    for (int b = 0; b < 2; ++b) {
        #pragma unroll
        for (int t = 0; t < 4; ++t) {
            int v = v_[t];
            a_dst[b][t] = smem_u32(&a_s[b][v * 32 + ((qq_ ^ (v & 7)) << 2)]);
        }
        w_dst[b] = smem_u32(&w_s[b][tid * 4]);  // rows pre-swizzled in g_wt
    }

    float c_[4][4];
    #pragma unroll
    for (int nt = 0; nt < 4; ++nt)
        c_[nt][0] = c_[nt][1] = c_[nt][2] = c_[nt][3] = 0.f;

    // issue gather for one stage into buffer b
    auto issue_stage = [&](int k, int b) {
        cp_async16(w_dst[b], g_wt + k * 1024 + tid * 4, 16);
        const int* nbr_k = g_nbr + (long long)k * N + obase;
        #pragma unroll
        for (int t = 0; t < 4; ++t) {
            int v = v_[t];
            int src = (obase + v < N) ? nbr_k[v] : -1;
            const float* gp = feats + (src >= 0 ? (long long)src * 32 + qq_ * 4 : 0);
            cp_async16(a_dst[b][t], gp, src >= 0 ? 16 : 0);
        }
        CP_COMMIT();
    };

    issue_stage(0, 0);  // prolog

    for (int k = 0; k < KVOL; ++k) {
        const int b = k & 1;
        CP_WAIT0();          // stage k copies (issued last iter) complete
        __syncthreads();     // publish stage k; retire stage k-1's readers

        if (k + 1 < KVOL) issue_stage(k + 1, b ^ 1);  // overlap with compute

        const float* ap = a_s[b];
        const float* wp = w_s[b];
        #pragma unroll
        for (int ks = 0; ks < 4; ++ks) {
            int col0 = ks * 8 + q, col1 = col0 + 4;
            int r0 = v0 + g, r1 = r0 + 8;
            uint32_t a0 = ld_a(ap, r0, col0);
            uint32_t a1 = ld_a(ap, r1, col0);
            uint32_t a2 = ld_a(ap, r0, col1);
            uint32_t a3 = ld_a(ap, r1, col1);
            #pragma unroll
            for (int nt = 0; nt < 4; ++nt) {
                int o = nt * 8 + g;
                uint32_t b0 = ld_b(wp, o, col0);
                uint32_t b1 = ld_b(wp, o, col1);
                asm volatile(
                    "mma.sync.aligned.m16n8k8.row.col.f32.tf32.tf32.f32 "
                    "{%0,%1,%2,%3}, {%4,%5,%6,%7}, {%8,%9}, {%0,%1,%2,%3};"
                    : "+f"(c_[nt][0]), "+f"(c_[nt][1]),
                      "+f"(c_[nt][2]), "+f"(c_[nt][3])
                    : "r"(a0), "r"(a1), "r"(a2), "r"(a3), "r"(b0), "r"(b1));
            }
        }
        __syncthreads();     // all warps done reading stage k before overwrite
    }

    // ---- epilogue: store pre-BN rows -------------------------------------
    int r0g = obase + v0 + g;
    int r1g = r0g + 8;
    #pragma unroll
    for (int nt = 0; nt < 4; ++nt) {
        if (r0g < N)
            *(float2*)(out + (long long)r0g * 32 + nt * 8 + 2 * q) =
                make_float2(c_[nt][0], c_[nt][1]);
        if (r1g < N)
            *(float2*)(out + (long long)r1g * 32 + nt * 8 + 2 * q) =
                make_float2(c_[nt][2], c_[nt][3]);
    }

    // ---- BN sums (padding rows are exactly zero, safe to include) --------
    float s[8], sq[8];
    #pragma unroll
    for (int nt = 0; nt < 4; ++nt) {
        s[nt * 2 + 0] = c_[nt][0] + c_[nt][2];
        s[nt * 2 + 1] = c_[nt][1] + c_[nt][3];
        sq[nt * 2 + 0] = c_[nt][0] * c_[nt][0] + c_[nt][2] * c_[nt][2];
        sq[nt * 2 + 1] = c_[nt][1] * c_[nt][1] + c_[nt][3] * c_[nt][3];
    }
    #pragma unroll
    for (int off = 16; off >= 4; off >>= 1) {
        #pragma unroll
        for (int e = 0; e < 8; ++e) {
            s[e]  += __shfl_xor_sync(~0u, s[e], off);
            sq[e] += __shfl_xor_sync(~0u, sq[e], off);
        }
    }
    if (lane < 4) {
        #pragma unroll
        for (int nt = 0; nt < 4; ++nt) {
            int ch = nt * 8 + 2 * lane;
            s_red[w * 32 + ch]           = s[nt * 2 + 0];
            s_red[w * 32 + ch + 1]       = s[nt * 2 + 1];
            s_red[256 + w * 32 + ch]     = sq[nt * 2 + 0];
            s_red[256 + w * 32 + ch + 1] = sq[nt * 2 + 1];
        }
    }
    __syncthreads();
    if (tid < 32) {
        float ts = 0.f, tq = 0.f;
        #pragma unroll
        for (int ww = 0; ww < 8; ++ww) {
            ts += s_red[ww * 32 + tid];
            tq += s_red[256 + ww * 32 + tid];
        }
        atomicAdd(&g_sum[tid], ts);
        atomicAdd(&g_sumsq[tid], tq);
    }
}

// ---------------------------------------------------------------------------
// K4: BN (batch stats, biased var) + ReLU, in place on out
// ---------------------------------------------------------------------------
__global__ void k_bnrelu(const float* __restrict__ gamma,
                         const float* __restrict__ beta,
                         float* __restrict__ out, int N) {
    __shared__ float s_scale[32], s_shift[32];
    int tid = threadIdx.x;
    if (tid < 32) {
        float invN = 1.0f / (float)N;
        float mean = g_sum[tid] * invN;
        float var  = g_sumsq[tid] * invN - mean * mean;
        float sc   = gamma[tid] * rsqrtf(var + 1e-5f);
        s_scale[tid] = sc;
        s_shift[tid] = fmaf(-mean, sc, beta[tid]);
    }
    __syncthreads();
    long long total = (long long)N * 8;
    for (long long j = blockIdx.x * (long long)blockDim.x + tid; j < total;
         j += (long long)gridDim.x * blockDim.x) {
        int c = ((int)(j & 7)) * 4;
        float4 v = *(const float4*)(out + j * 4);
        float4 r;
        r.x = fmaxf(fmaf(v.x, s_scale[c + 0], s_shift[c + 0]), 0.f);
        r.y = fmaxf(fmaf(v.y, s_scale[c + 1], s_shift[c + 1]), 0.f);
        r.z = fmaxf(fmaf(v.z, s_scale[c + 2], s_shift[c + 2]), 0.f);
        r.w = fmaxf(fmaf(v.w, s_scale[c + 3], s_shift[c + 3]), 0.f);
        *(float4*)(out + j * 4) = r;
    }
}

// ---------------------------------------------------------------------------
// Launch. Inputs: feats, W, gamma, beta, in_idx, out_idx, mask (mask unused)
// ---------------------------------------------------------------------------
extern "C" void kernel_launch(void* const* d_in, const int* in_sizes, int n_in,
                              void* d_out, int out_size) {
    const float* feats   = (const float*)d_in[0];
    const float* W       = (const float*)d_in[1];
    const float* gamma   = (const float*)d_in[2];
    const float* beta    = (const float*)d_in[3];
    const int*   in_idx  = (const int*)d_in[4];
    const int*   out_idx = (const int*)d_in[5];
    const int N = in_sizes[0] / 32;
    float* out = (float*)d_out;

    k_init<<<1024, 256>>>(KVOL * N);
    dim3 sg((N + 255) / 256, KVOL);
    k_scatter<<<sg, 256>>>(out_idx, in_idx, N);
    k_wt<<<KVOL, 256>>>(W);
    k_conv_mma<<<(N + TILE_M - 1) / TILE_M, 256>>>(feats, out, N);
    k_bnrelu<<<1024, 256>>>(gamma, beta, out, N);
}